// round 14
// baseline (speedup 1.0000x reference)
#include <cuda_runtime.h>
#include <cstdint>

#define SEQ   4096
#define EMB   300
#define K_IN  600      // 2*EMB
#define HID   500
#define JPAD  512      // padded hidden
#define GPAD  2048     // padded gate rows (4*JPAD)
#define NCTA  64       // recurrence CTAs: 64 x 8 warps = 512 warps = JPAD units
#define CTHR  256

// ---------------- scratch (static device globals; no allocation) -----------
__device__ float g_X[(size_t)SEQ * K_IN];                  // gathered inputs
__device__ float g_pre[(size_t)SEQ * GPAD];                // pre-activations, remapped
__device__ unsigned long long g_ht[2][JPAD];               // tagged h: {tag<<32 | f32}

// ---------------- fast activations (MUFU ex2/rcp) --------------------------
__device__ __forceinline__ float fex2(float x){ float y; asm("ex2.approx.f32 %0,%1;":"=f"(y):"f"(x)); return y; }
__device__ __forceinline__ float frcp(float x){ float y; asm("rcp.approx.f32 %0,%1;":"=f"(y):"f"(x)); return y; }
__device__ __forceinline__ float ftanh(float x){ float e = fex2(2.88539008f * x); return 1.0f - 2.0f * frcp(e + 1.0f); }

__device__ __forceinline__ unsigned long long pack2(float a, float b){
    unsigned long long r; asm("mov.b64 %0,{%1,%2};" : "=l"(r) : "f"(a), "f"(b)); return r;
}
__device__ __forceinline__ void fma2(unsigned long long& acc, unsigned long long a, unsigned long long b){
    asm("fma.rn.f32x2 %0, %1, %2, %0;" : "+l"(acc) : "l"(a), "l"(b));
}

// tagged-packet helpers ------------------------------------------------------
__device__ __forceinline__ void ld_pair_cg(const unsigned long long* p,
                                           unsigned long long& a, unsigned long long& b){
    asm volatile("ld.global.cg.v2.u64 {%0,%1}, [%2];"
                 : "=l"(a), "=l"(b) : "l"(p) : "memory");
}
__device__ __forceinline__ void st_pkt_cg(unsigned long long* p, unsigned long long v){
    asm volatile("st.global.cg.u64 [%0], %1;" :: "l"(p), "l"(v) : "memory");
}
__device__ __forceinline__ int   pkt_tag(unsigned long long v){ return (int)(v >> 32); }
__device__ __forceinline__ float pkt_val(unsigned long long v){ return __uint_as_float((unsigned)v); }
__device__ __forceinline__ unsigned long long mk_pkt(int tag, float h){
    return ((unsigned long long)(unsigned)tag << 32) | __float_as_uint(h);
}

// ---------------- kernel 1: seed step-0 h and invalidate buffer 1 -----------
__global__ void k_reset()
{
    int i = threadIdx.x;
    if (i < JPAD) {
        g_ht[0][i] = mk_pkt(0, 0.0f);     // h(0) = 0, tag 0
        g_ht[1][i] = mk_pkt(-1, 0.0f);    // invalid
    }
}

// ---------------- kernel 2: embedding gather + concat -----------------------
__global__ void k_gather(const int* __restrict__ words, const int* __restrict__ labels,
                         const float* __restrict__ ew,  const float* __restrict__ ee)
{
    int id = blockIdx.x * blockDim.x + threadIdx.x;
    int t = id / K_IN;
    int k = id - t * K_IN;
    float v = (k < EMB) ? ew[(size_t)words[t]  * EMB + k]
                        : ee[(size_t)labels[t] * EMB + (k - EMB)];
    g_X[id] = v;
}

// ---------------- kernel 3: pre = X @ W_ih^T + (b_ih + b_hh), remapped ------
// Global gate row R in [0,2048):
//   unit j = ((R>>5)<<3) | ((R>>2)&7),  gate g = R&3  (4 gates contiguous)
__global__ void __launch_bounds__(256) k_gemm(const float* __restrict__ W,
                                              const float* __restrict__ bi,
                                              const float* __restrict__ bh)
{
    __shared__ float xs[8][64];
    __shared__ float ws[8][68];

    int t0 = blockIdx.x * 64;
    int R0 = blockIdx.y * 64;
    int tid = threadIdx.x;
    int tx = tid & 15;
    int ty = tid >> 4;

    float acc[4][4];
#pragma unroll
    for (int i = 0; i < 4; i++)
#pragma unroll
        for (int j = 0; j < 4; j++) acc[i][j] = 0.0f;

    for (int k0 = 0; k0 < K_IN; k0 += 8) {
#pragma unroll
        for (int p = 0; p < 2; p++) {
            int e  = tid + p * 256;
            int kk = e >> 6;
            int rr = e & 63;
            int R = R0 + rr;
            int g  = R & 3;
            int j  = ((R >> 5) << 3) | ((R >> 2) & 7);
            float wv = 0.0f;
            if (j < HID) wv = W[(size_t)(g * HID + j) * K_IN + (k0 + kk)];
            ws[kk][rr] = wv;
            xs[kk][rr] = g_X[(size_t)(t0 + rr) * K_IN + (k0 + kk)];
        }
        __syncthreads();
#pragma unroll
        for (int kk = 0; kk < 8; kk++) {
            float a[4], x[4];
#pragma unroll
            for (int i = 0; i < 4; i++) a[i] = ws[kk][ty + 16 * i];
#pragma unroll
            for (int j = 0; j < 4; j++) x[j] = xs[kk][tx + 16 * j];
#pragma unroll
            for (int i = 0; i < 4; i++)
#pragma unroll
                for (int j = 0; j < 4; j++) acc[i][j] += a[i] * x[j];
        }
        __syncthreads();
    }

#pragma unroll
    for (int i = 0; i < 4; i++) {
        int R = R0 + ty + 16 * i;
        int g  = R & 3;
        int j  = ((R >> 5) << 3) | ((R >> 2) & 7);
        bool valid = (j < HID);
        float bb = valid ? (bi[g * HID + j] + bh[g * HID + j]) : 0.0f;
#pragma unroll
        for (int jx = 0; jx < 4; jx++) {
            int t = t0 + tx + 16 * jx;
            g_pre[(size_t)t * GPAD + R] = valid ? (acc[i][jx] + bb) : 0.0f;
        }
    }
}

// ---------------- kernel 4: tagged-data LSTM, CTA-cooperative staging --------
// R13 poll/publish protocol byte-identical. Changes (all intra-warp tail):
//   - transposed reduce: xor16,xor8 on 4 gates, then group q=lane>>3 takes
//     gate q and finishes with xor4,2,1 (11 SHFLs vs 20, depth 5)
//   - branchless unified activation on ALL lanes: act = A*rcp(1+ex2(B*x))+C
//     (A,B,C per group; tanh == 2*sig(2x)-1) -- no divergence
//   - double-buffered smem h -> ONE __syncthreads per step (reads of buffer b
//     at step t precede bar(t+1), which precedes deposits into b at t+2)
__global__ void __launch_bounds__(CTHR, 1)
k_lstm(const float* __restrict__ Whh, const float* __restrict__ fcw,
       const float* __restrict__ fcb, float* __restrict__ out)
{
    __shared__ float sh_h[2][JPAD];     // double buffer

    const int tid  = threadIdx.x;
    const int blk  = blockIdx.x;
    const int w    = tid >> 5;          // warp id = unit within CTA + poll chunk
    const int lane = tid & 31;
    const int j    = blk * 8 + w;       // this warp's hidden unit
    const int q    = lane >> 3;         // this lane's gate group (0..3)

    // per-group activation constants: gates 0,1,3 sigmoid; gate 2 tanh
    const float actA = (q == 2) ?  2.0f         : 1.0f;
    const float actB = (q == 2) ? -2.88539008f  : -1.44269504f;
    const float actC = (q == 2) ? -1.0f         : 0.0f;

    // register-resident W_hh: 4 gates x 8 packed pairs, k = 2*lane + 64*m
    unsigned long long w2[4][8];
#pragma unroll
    for (int g = 0; g < 4; g++) {
#pragma unroll
        for (int m = 0; m < 8; m++) {
            int k = 2 * lane + 64 * m;
            float a = 0.0f, b = 0.0f;
            if (j < HID) {
                const float* row = Whh + (size_t)(g * HID + j) * HID;
                if (k     < HID) a = row[k];
                if (k + 1 < HID) b = row[k + 1];
            }
            w2[g][m] = pack2(a, b);
        }
    }

    float c = 0.0f;                                  // cell state (lane 0)
    const float* preQ = g_pre + (size_t)blk * 32 + w * 4 + q;
    const int    pidx = 64 * w + 2 * lane;           // this thread's poll pair

#pragma unroll 1
    for (int t = 0; t < SEQ; t++) {
        // every lane prefetches its gate's pre (4 addrs, one 16B sector)
        float pvg = __ldg(preQ + (size_t)t * GPAD);

        // ---- poll own 512B chunk of h(t); retry only stale pairs (R4) -----
        {
            const unsigned long long* hb = g_ht[t & 1];
            unsigned long long va, vb;
            ld_pair_cg(&hb[pidx], va, vb);
            for (;;) {
                bool stale = (pkt_tag(va) != t) | (pkt_tag(vb) != t);
                if (!__any_sync(0xffffffffu, stale)) break;
                if (stale) ld_pair_cg(&hb[pidx], va, vb);
            }
            ((float2*)sh_h[t & 1])[32 * w + lane] = make_float2(pkt_val(va), pkt_val(vb));
        }
        __syncthreads();

        // ---- matvec: 4 gates x 8 packed FMAs from smem --------------------
        unsigned long long acc2[4] = {0ull, 0ull, 0ull, 0ull};
        const float2* sh2 = (const float2*)sh_h[t & 1];
#pragma unroll
        for (int m = 0; m < 8; m++) {
            float2 hv = sh2[lane + 32 * m];
            unsigned long long h2 = pack2(hv.x, hv.y);
#pragma unroll
            for (int g = 0; g < 4; g++)
                fma2(acc2[g], w2[g][m], h2);
        }

        // ---- transposed reduce: xor16,xor8 on 4 gates; then gate q only ---
        float s[4];
#pragma unroll
        for (int g = 0; g < 4; g++) {
            float lo = __uint_as_float((unsigned)acc2[g]);
            float hi = __uint_as_float((unsigned)(acc2[g] >> 32));
            s[g] = lo + hi;
        }
#pragma unroll
        for (int g = 0; g < 4; g++) s[g] += __shfl_xor_sync(0xffffffffu, s[g], 16);
#pragma unroll
        for (int g = 0; g < 4; g++) s[g] += __shfl_xor_sync(0xffffffffu, s[g], 8);

        float v = (q == 0) ? s[0] : (q == 1) ? s[1] : (q == 2) ? s[2] : s[3];
        v += __shfl_xor_sync(0xffffffffu, v, 4);
        v += __shfl_xor_sync(0xffffffffu, v, 2);
        v += __shfl_xor_sync(0xffffffffu, v, 1);
        // now every lane of group q holds gate q's full sum

        // ---- branchless activation on all lanes ---------------------------
        float x   = v + pvg;
        float act = fmaf(actA, frcp(1.0f + fex2(actB * x)), actC);

        // ---- gather + cell update + publish (lane 0) ----------------------
        float gf = __shfl_sync(0xffffffffu, act, 8);
        float gg = __shfl_sync(0xffffffffu, act, 16);
        float go = __shfl_sync(0xffffffffu, act, 24);
        if (lane == 0) {
            c = gf * c + act * gg;            // act on lane 0 == gate i
            float h = go * ftanh(c);
            st_pkt_cg(&g_ht[(t + 1) & 1][j], mk_pkt(t + 1, h));
        }
    }

    // ---------------- final FC: out[20] = fc_w @ h(SEQ) + fc_b (CTA 0) ------
    if (blk == 0) {
        const unsigned long long* hb = g_ht[SEQ & 1];
        unsigned long long va, vb;
        ld_pair_cg(&hb[pidx], va, vb);
        for (;;) {
            bool stale = (pkt_tag(va) != SEQ) | (pkt_tag(vb) != SEQ);
            if (!__any_sync(0xffffffffu, stale)) break;
            if (stale) ld_pair_cg(&hb[pidx], va, vb);
        }
        ((float2*)sh_h[0])[32 * w + lane] = make_float2(pkt_val(va), pkt_val(vb));
        __syncthreads();

        const float* hL = sh_h[0];
#pragma unroll 1
        for (int o = w; o < 20; o += 8) {
            float a = 0.0f;
#pragma unroll
            for (int m = 0; m < 16; m++) {
                int k = lane + 32 * m;
                if (k < HID) a += fcw[(size_t)o * HID + k] * hL[k];
            }
#pragma unroll
            for (int d = 16; d >= 1; d >>= 1)
                a += __shfl_xor_sync(0xffffffffu, a, d);
            if (lane == 0) out[o] = a + fcb[o];
        }
    }
}

// ---------------- launch ----------------------------------------------------
extern "C" void kernel_launch(void* const* d_in, const int* in_sizes, int n_in,
                              void* d_out, int out_size)
{
    const int*   words  = (const int*)  d_in[0];
    const int*   labels = (const int*)  d_in[1];
    const float* ew     = (const float*)d_in[2];
    const float* ee     = (const float*)d_in[3];
    const float* W_ih   = (const float*)d_in[4];
    const float* W_hh   = (const float*)d_in[5];
    const float* b_ih   = (const float*)d_in[6];
    const float* b_hh   = (const float*)d_in[7];
    const float* fc_w   = (const float*)d_in[8];
    const float* fc_b   = (const float*)d_in[9];
    float* out = (float*)d_out;

    k_reset<<<1, JPAD>>>();
    k_gather<<<(SEQ * K_IN) / 1024, 1024>>>(words, labels, ew, ee);
    k_gemm<<<dim3(SEQ / 64, GPAD / 64), 256>>>(W_ih, b_ih, b_hh);
    k_lstm<<<NCTA, CTHR>>>(W_hh, fc_w, fc_b, out);
}

// round 17
// speedup vs baseline: 1.4407x; 1.4407x over previous
#include <cuda_runtime.h>
#include <cstdint>

#define SEQ   4096
#define EMB   300
#define K_IN  600      // 2*EMB
#define HID   500
#define JPAD  512      // padded hidden
#define GPAD  2048     // padded gate rows (4*JPAD)
#define NCTA  64       // recurrence CTAs: 64 x 8 warps = 512 warps = JPAD units
#define CTHR  256
#define NREP  4        // h-buffer replicas (spreads poll load across L2 slices)

// ---------------- scratch (static device globals; no allocation) -----------
__device__ float g_X[(size_t)SEQ * K_IN];                  // gathered inputs
__device__ float g_pre[(size_t)SEQ * GPAD];                // pre-activations, remapped
__device__ unsigned long long g_ht[2][NREP][JPAD];         // tagged h replicas

// ---------------- fast activations (MUFU ex2/rcp) --------------------------
__device__ __forceinline__ float fex2(float x){ float y; asm("ex2.approx.f32 %0,%1;":"=f"(y):"f"(x)); return y; }
__device__ __forceinline__ float frcp(float x){ float y; asm("rcp.approx.f32 %0,%1;":"=f"(y):"f"(x)); return y; }
__device__ __forceinline__ float fsig (float x){ return frcp(1.0f + fex2(-1.44269504f * x)); }
__device__ __forceinline__ float ftanh(float x){ float e = fex2(2.88539008f * x); return 1.0f - 2.0f * frcp(e + 1.0f); }

__device__ __forceinline__ unsigned long long pack2(float a, float b){
    unsigned long long r; asm("mov.b64 %0,{%1,%2};" : "=l"(r) : "f"(a), "f"(b)); return r;
}
__device__ __forceinline__ void fma2(unsigned long long& acc, unsigned long long a, unsigned long long b){
    asm("fma.rn.f32x2 %0, %1, %2, %0;" : "+l"(acc) : "l"(a), "l"(b));
}

// tagged-packet helpers ------------------------------------------------------
__device__ __forceinline__ void ld_pair_cg(const unsigned long long* p,
                                           unsigned long long& a, unsigned long long& b){
    asm volatile("ld.global.cg.v2.u64 {%0,%1}, [%2];"
                 : "=l"(a), "=l"(b) : "l"(p) : "memory");
}
__device__ __forceinline__ void st_pkt_cg(unsigned long long* p, unsigned long long v){
    asm volatile("st.global.cg.u64 [%0], %1;" :: "l"(p), "l"(v) : "memory");
}
__device__ __forceinline__ int   pkt_tag(unsigned long long v){ return (int)(v >> 32); }
__device__ __forceinline__ float pkt_val(unsigned long long v){ return __uint_as_float((unsigned)v); }
__device__ __forceinline__ unsigned long long mk_pkt(int tag, float h){
    return ((unsigned long long)(unsigned)tag << 32) | __float_as_uint(h);
}

// ---------------- kernel 1: seed step-0 h and invalidate buffer 1 -----------
__global__ void k_reset()
{
    int i = threadIdx.x;
    if (i < JPAD) {
#pragma unroll
        for (int r = 0; r < NREP; r++) {
            g_ht[0][r][i] = mk_pkt(0, 0.0f);     // h(0) = 0, tag 0
            g_ht[1][r][i] = mk_pkt(-1, 0.0f);    // invalid
        }
    }
}

// ---------------- kernel 2: embedding gather + concat -----------------------
__global__ void k_gather(const int* __restrict__ words, const int* __restrict__ labels,
                         const float* __restrict__ ew,  const float* __restrict__ ee)
{
    int id = blockIdx.x * blockDim.x + threadIdx.x;
    int t = id / K_IN;
    int k = id - t * K_IN;
    float v = (k < EMB) ? ew[(size_t)words[t]  * EMB + k]
                        : ee[(size_t)labels[t] * EMB + (k - EMB)];
    g_X[id] = v;
}

// ---------------- kernel 3: pre = X @ W_ih^T + (b_ih + b_hh), remapped ------
// Global gate row R in [0,2048):
//   unit j = ((R>>5)<<3) | ((R>>2)&7),  gate g = R&3  (4 gates contiguous)
__global__ void __launch_bounds__(256) k_gemm(const float* __restrict__ W,
                                              const float* __restrict__ bi,
                                              const float* __restrict__ bh)
{
    __shared__ float xs[8][64];
    __shared__ float ws[8][68];

    int t0 = blockIdx.x * 64;
    int R0 = blockIdx.y * 64;
    int tid = threadIdx.x;
    int tx = tid & 15;
    int ty = tid >> 4;

    float acc[4][4];
#pragma unroll
    for (int i = 0; i < 4; i++)
#pragma unroll
        for (int j = 0; j < 4; j++) acc[i][j] = 0.0f;

    for (int k0 = 0; k0 < K_IN; k0 += 8) {
#pragma unroll
        for (int p = 0; p < 2; p++) {
            int e  = tid + p * 256;
            int kk = e >> 6;
            int rr = e & 63;
            int R = R0 + rr;
            int g  = R & 3;
            int j  = ((R >> 5) << 3) | ((R >> 2) & 7);
            float wv = 0.0f;
            if (j < HID) wv = W[(size_t)(g * HID + j) * K_IN + (k0 + kk)];
            ws[kk][rr] = wv;
            xs[kk][rr] = g_X[(size_t)(t0 + rr) * K_IN + (k0 + kk)];
        }
        __syncthreads();
#pragma unroll
        for (int kk = 0; kk < 8; kk++) {
            float a[4], x[4];
#pragma unroll
            for (int i = 0; i < 4; i++) a[i] = ws[kk][ty + 16 * i];
#pragma unroll
            for (int j = 0; j < 4; j++) x[j] = xs[kk][tx + 16 * j];
#pragma unroll
            for (int i = 0; i < 4; i++)
#pragma unroll
                for (int j = 0; j < 4; j++) acc[i][j] += a[i] * x[j];
        }
        __syncthreads();
    }

#pragma unroll
    for (int i = 0; i < 4; i++) {
        int R = R0 + ty + 16 * i;
        int g  = R & 3;
        int j  = ((R >> 5) << 3) | ((R >> 2) & 7);
        bool valid = (j < HID);
        float bb = valid ? (bi[g * HID + j] + bh[g * HID + j]) : 0.0f;
#pragma unroll
        for (int jx = 0; jx < 4; jx++) {
            int t = t0 + tx + 16 * jx;
            g_pre[(size_t)t * GPAD + R] = valid ? (acc[i][jx] + bb) : 0.0f;
        }
    }
}

// ---------------- kernel 4: tagged-data LSTM, CTA-cooperative staging --------
// EXACT R13 structure (proven 5.71ms). ONE change: the tagged h buffer is
// replicated NREP=4x. Producers broadcast h to lanes 0-3 (1 SHFL) and each
// lane stores one replica; consumer CTA blk polls only replica blk&3. This
// cuts per-L2-line poll pressure 4x (64 -> 16 warps/line), relieving the
// per-slice queueing that inflates publish->observe latency.
__global__ void __launch_bounds__(CTHR, 1)
k_lstm(const float* __restrict__ Whh, const float* __restrict__ fcw,
       const float* __restrict__ fcb, float* __restrict__ out)
{
    __shared__ float sh_h[JPAD];

    const int tid  = threadIdx.x;
    const int blk  = blockIdx.x;
    const int w    = tid >> 5;          // warp id = unit within CTA + poll chunk
    const int lane = tid & 31;
    const int j    = blk * 8 + w;       // this warp's hidden unit
    const int rep  = blk & (NREP - 1);  // replica this CTA polls

    // register-resident W_hh: 4 gates x 8 packed pairs, k = 2*lane + 64*m
    unsigned long long w2[4][8];
#pragma unroll
    for (int g = 0; g < 4; g++) {
#pragma unroll
        for (int m = 0; m < 8; m++) {
            int k = 2 * lane + 64 * m;
            float a = 0.0f, b = 0.0f;
            if (j < HID) {
                const float* row = Whh + (size_t)(g * HID + j) * HID;
                if (k     < HID) a = row[k];
                if (k + 1 < HID) b = row[k + 1];
            }
            w2[g][m] = pack2(a, b);
        }
    }

    float c = 0.0f;                                  // cell state (lane 0)
    const float* preB = g_pre + (size_t)blk * 32 + w * 4;
    const int    pidx = 64 * w + 2 * lane;           // this thread's poll pair

#pragma unroll 1
    for (int t = 0; t < SEQ; t++) {
        // lanes 0-3 prefetch their own gate's pre-activation (one 16B sector)
        float pvg = 0.0f;
        if (lane < 4)
            pvg = __ldg(preB + (size_t)t * GPAD + lane);

        // ---- poll own 512B chunk of replica rep of h(t) -------------------
        {
            const unsigned long long* hb = g_ht[t & 1][rep];
            unsigned long long va, vb;
            ld_pair_cg(&hb[pidx], va, vb);
            for (;;) {
                bool stale = (pkt_tag(va) != t) | (pkt_tag(vb) != t);
                if (!__any_sync(0xffffffffu, stale)) break;
                if (stale) ld_pair_cg(&hb[pidx], va, vb);
            }
            ((float2*)sh_h)[32 * w + lane] = make_float2(pkt_val(va), pkt_val(vb));
        }
        __syncthreads();

        // ---- matvec: 4 gates x 8 packed FMAs from smem --------------------
        unsigned long long acc2[4] = {0ull, 0ull, 0ull, 0ull};
        const float2* sh2 = (const float2*)sh_h;
#pragma unroll
        for (int m = 0; m < 8; m++) {
            float2 hv = sh2[lane + 32 * m];
            unsigned long long h2 = pack2(hv.x, hv.y);
#pragma unroll
            for (int g = 0; g < 4; g++)
                fma2(acc2[g], w2[g][m], h2);
        }
        __syncthreads();    // sh_h fully consumed; safe to refill next iter

        // ---- butterfly reduce (4 gates interleaved; all lanes get sums) ---
        float s[4];
#pragma unroll
        for (int g = 0; g < 4; g++) {
            float lo = __uint_as_float((unsigned)acc2[g]);
            float hi = __uint_as_float((unsigned)(acc2[g] >> 32));
            s[g] = lo + hi;
        }
#pragma unroll
        for (int d = 16; d >= 1; d >>= 1)
#pragma unroll
            for (int g = 0; g < 4; g++)
                s[g] += __shfl_xor_sync(0xffffffffu, s[g], d);

        // ---- parallel activations on lanes 0-3; publish to all replicas --
        if (lane < 4) {
            float x = (lane == 0) ? s[0] : (lane == 1) ? s[1]
                    : (lane == 2) ? s[2] : s[3];
            x += pvg;
            float act = (lane == 2) ? ftanh(x) : fsig(x);
            float gi = __shfl_sync(0x0000000fu, act, 0);
            float gf = __shfl_sync(0x0000000fu, act, 1);
            float gg = __shfl_sync(0x0000000fu, act, 2);
            float go = __shfl_sync(0x0000000fu, act, 3);
            float h = 0.0f;
            if (lane == 0) {
                c = gf * c + gi * gg;
                h = go * ftanh(c);
            }
            h = __shfl_sync(0x0000000fu, h, 0);      // broadcast to lanes 0-3
            st_pkt_cg(&g_ht[(t + 1) & 1][lane][j], mk_pkt(t + 1, h));
        }
    }

    // ---------------- final FC: out[20] = fc_w @ h(SEQ) + fc_b (CTA 0) ------
    if (blk == 0) {
        // poll h(SEQ) (replica 0) into smem
        const unsigned long long* hb = g_ht[SEQ & 1][0];
        unsigned long long va, vb;
        ld_pair_cg(&hb[pidx], va, vb);
        for (;;) {
            bool stale = (pkt_tag(va) != SEQ) | (pkt_tag(vb) != SEQ);
            if (!__any_sync(0xffffffffu, stale)) break;
            if (stale) ld_pair_cg(&hb[pidx], va, vb);
        }
        ((float2*)sh_h)[32 * w + lane] = make_float2(pkt_val(va), pkt_val(vb));
        __syncthreads();

#pragma unroll 1
        for (int o = w; o < 20; o += 8) {
            float a = 0.0f;
#pragma unroll
            for (int m = 0; m < 16; m++) {
                int k = lane + 32 * m;
                if (k < HID) a += fcw[(size_t)o * HID + k] * sh_h[k];
            }
#pragma unroll
            for (int d = 16; d >= 1; d >>= 1)
                a += __shfl_xor_sync(0xffffffffu, a, d);
            if (lane == 0) out[o] = a + fcb[o];
        }
    }
}

// ---------------- launch ----------------------------------------------------
extern "C" void kernel_launch(void* const* d_in, const int* in_sizes, int n_in,
                              void* d_out, int out_size)
{
    const int*   words  = (const int*)  d_in[0];
    const int*   labels = (const int*)  d_in[1];
    const float* ew     = (const float*)d_in[2];
    const float* ee     = (const float*)d_in[3];
    const float* W_ih   = (const float*)d_in[4];
    const float* W_hh   = (const float*)d_in[5];
    const float* b_ih   = (const float*)d_in[6];
    const float* b_hh   = (const float*)d_in[7];
    const float* fc_w   = (const float*)d_in[8];
    const float* fc_b   = (const float*)d_in[9];
    float* out = (float*)d_out;

    k_reset<<<1, JPAD>>>();
    k_gather<<<(SEQ * K_IN) / 1024, 1024>>>(words, labels, ew, ee);
    k_gemm<<<dim3(SEQ / 64, GPAD / 64), 256>>>(W_ih, b_ih, b_hh);
    k_lstm<<<NCTA, CTHR>>>(W_hh, fc_w, fc_b, out);
}